// round 12
// baseline (speedup 1.0000x reference)
#include <cuda_runtime.h>
#include <cuda_bf16.h>
#include <cstdint>
#include <cstring>

#define SEQ 4096
#define TQ  64
#define WIN 256
#define NB  4

// per-buffer smem offsets (bf16 tiles, swizzled images)
#define KH 0
#define KL 8192
#define VH 16384
#define VL 24576
#define BUF 32768
#define NSTAGE 3
#define SMEM_TOTAL (NSTAGE * BUF)
#define SMROW 68                     // merge buffer row stride (floats)

// precomputed bf16 hi/lo K/V tiles, stored as exact swizzled smem images
__device__ char g_kv[(size_t)NB * (SEQ / 64) * BUF];

__device__ __forceinline__ uint32_t smem_u32(const void* p) {
    uint32_t a;
    asm("{ .reg .u64 t; cvta.to.shared.u64 t, %1; cvt.u32.u64 %0, t; }" : "=r"(a) : "l"(p));
    return a;
}
__device__ __forceinline__ float ex2(float x) {
    float r; asm("ex2.approx.ftz.f32 %0, %1;" : "=f"(r) : "f"(x)); return r;
}
__device__ __forceinline__ void ldsm4(uint32_t& r0, uint32_t& r1, uint32_t& r2, uint32_t& r3, uint32_t a) {
    asm volatile("ldmatrix.sync.aligned.m8n8.x4.shared.b16 {%0,%1,%2,%3}, [%4];"
                 : "=r"(r0), "=r"(r1), "=r"(r2), "=r"(r3) : "r"(a));
}
__device__ __forceinline__ void ldsm4t(uint32_t& r0, uint32_t& r1, uint32_t& r2, uint32_t& r3, uint32_t a) {
    asm volatile("ldmatrix.sync.aligned.m8n8.x4.trans.shared.b16 {%0,%1,%2,%3}, [%4];"
                 : "=r"(r0), "=r"(r1), "=r"(r2), "=r"(r3) : "r"(a));
}
__device__ __forceinline__ void mma4(float (&d)[4], uint32_t a0, uint32_t a1, uint32_t a2, uint32_t a3,
                                     uint32_t b0, uint32_t b1) {
    asm volatile("mma.sync.aligned.m16n8k16.row.col.f32.bf16.bf16.f32 "
                 "{%0,%1,%2,%3}, {%4,%5,%6,%7}, {%8,%9}, {%0,%1,%2,%3};"
                 : "+f"(d[0]), "+f"(d[1]), "+f"(d[2]), "+f"(d[3])
                 : "r"(a0), "r"(a1), "r"(a2), "r"(a3), "r"(b0), "r"(b1));
}
__device__ __forceinline__ uint32_t packbf(float x, float y) {
    __nv_bfloat162 v = __floats2bfloat162_rn(x, y);
    uint32_t u; memcpy(&u, &v, 4); return u;
}
__device__ __forceinline__ void splitp(float x, float y, uint32_t& h, uint32_t& l) {
    __nv_bfloat16 hx = __float2bfloat16(x), hy = __float2bfloat16(y);
    h = ((uint32_t)__bfloat16_as_ushort(hy) << 16) | __bfloat16_as_ushort(hx);
    l = packbf(x - __bfloat162float(hx), y - __bfloat162float(hy));
}

// ---- precompute: fp32 K/V -> bf16 hi/lo swizzled tile images (once) ----
__global__ __launch_bounds__(256) void conv_kernel(const float* __restrict__ qkv)
{
    const int ti = blockIdx.x, b = blockIdx.y, tid = threadIdx.x;
    const int r = tid & 63, isV = (tid >> 6) & 1, hf = tid >> 7;
    const float4* src = reinterpret_cast<const float4*>(
        qkv + ((size_t)b * SEQ + ti * 64 + r) * 192 + 64 + isV * 64);
    char* base = g_kv + ((size_t)(b * (SEQ / 64) + ti)) * BUF + (isV ? VH : KH);
    char* hb = base + r * 128;
    char* lb = base + 8192 + r * 128;
    const uint32_t xr = (r & 7) << 4;
    #pragma unroll
    for (int u = 0; u < 4; u++) {
        int gi = hf * 4 + u;
        float4 f0 = src[2 * gi], f1 = src[2 * gi + 1];
        uint4 hv, lv;
        splitp(f0.x, f0.y, hv.x, lv.x);
        splitp(f0.z, f0.w, hv.y, lv.y);
        splitp(f1.x, f1.y, hv.z, lv.z);
        splitp(f1.z, f1.w, hv.w, lv.w);
        uint32_t off = (uint32_t)(gi * 16) ^ xr;
        *reinterpret_cast<uint4*>(hb + off) = hv;
        *reinterpret_cast<uint4*>(lb + off) = lv;
    }
}

// async copy of one precomputed 32KB tile image into an smem stage (256 thr).
// ALWAYS commits a group (possibly empty) so wait_group counting stays aligned.
__device__ __forceinline__ void prefetch_tile(uint32_t sbu, const char* gkv,
                                              int j, int n, int tid) {
    if (j < n) {
        uint32_t dst = sbu + (uint32_t)((j % NSTAGE) * BUF);
        const char* src = gkv + (size_t)j * BUF;
        #pragma unroll
        for (int c = 0; c < 8; c++) {
            uint32_t off = (uint32_t)(tid * 16 + c * 4096);
            asm volatile("cp.async.cg.shared.global [%0], [%1], 16;"
                         :: "r"(dst + off), "l"(src + off));
        }
    }
    asm volatile("cp.async.commit_group;" ::: "memory");
}

// MODE: 0 unmasked, 1 diagonal (valid j<=iq), 2 lowest (valid j>=iq-WIN)
// G: key half of this warp group (0: keys 0-31; 1: keys 32-63). NO barriers inside.
template<int MODE, int G>
__device__ __forceinline__ void compute_tile(int k0, int tid, uint32_t sb,
                                             const uint32_t (&qh)[4][4], const uint32_t (&ql)[4][4],
                                             float (&o)[8][4], float& l0acc, float& l1acc,
                                             int iq0, int iq1)
{
    const int lane = tid & 31, wq = (tid >> 5) & 3;
    const int t = lane & 3;
    const int rk = lane & 7;
    const uint32_t xorl = rk << 4;
    const uint32_t m16  = (lane >> 3) * 16;

    // ---- S = Q·K^T (split bf16) over this group's 4 key n-tiles ----
    float s[4][4] = {};
    #pragma unroll
    for (int c = 0; c < 4; c += 2) {
        #pragma unroll
        for (int ntl = 0; ntl < 4; ntl++) {
            const int nt = G * 4 + ntl;
            if (MODE == 1 && nt >= 2 * wq + 2) continue;
            if (MODE == 2 && nt < 2 * wq) continue;
            uint32_t base = sb + (uint32_t)(nt * 1024 + rk * 128) + ((uint32_t)(c * 32 + m16) ^ xorl);
            uint32_t kh0, kh1, kh2, kh3, kl0, kl1, kl2, kl3;
            ldsm4(kh0, kh1, kh2, kh3, base + KH);
            ldsm4(kl0, kl1, kl2, kl3, base + KL);
            mma4(s[ntl], qh[c][0], qh[c][1], qh[c][2], qh[c][3], kh0, kh1);
            mma4(s[ntl], qh[c+1][0], qh[c+1][1], qh[c+1][2], qh[c+1][3], kh2, kh3);
            mma4(s[ntl], ql[c][0], ql[c][1], ql[c][2], ql[c][3], kh0, kh1);
            mma4(s[ntl], ql[c+1][0], ql[c+1][1], ql[c+1][2], ql[c+1][3], kh2, kh3);
            mma4(s[ntl], qh[c][0], qh[c][1], qh[c][2], qh[c][3], kl0, kl1);
            mma4(s[ntl], qh[c+1][0], qh[c+1][1], qh[c+1][2], qh[c+1][3], kl2, kl3);
        }
    }

    // ---- softmax (static max): p = valid ? 2^s : 0 ----
    uint32_t ph[4], phB[4], pl[4], plB[4];
    #pragma unroll
    for (int ntl = 0; ntl < 4; ntl++) {
        int j0 = k0 + (G * 4 + ntl) * 8 + 2 * t, j1 = j0 + 1;
        bool v00 = true, v01 = true, v10 = true, v11 = true;
        if (MODE == 1) { v00 = j0 <= iq0; v01 = j1 <= iq0; v10 = j0 <= iq1; v11 = j1 <= iq1; }
        if (MODE == 2) { v00 = j0 >= iq0 - WIN; v01 = j1 >= iq0 - WIN;
                         v10 = j0 >= iq1 - WIN; v11 = j1 >= iq1 - WIN; }
        float p0 = v00 ? ex2(s[ntl][0]) : 0.0f;
        float p1 = v01 ? ex2(s[ntl][1]) : 0.0f;
        float p2 = v10 ? ex2(s[ntl][2]) : 0.0f;
        float p3 = v11 ? ex2(s[ntl][3]) : 0.0f;
        l0acc += p0 + p1;
        l1acc += p2 + p3;
        splitp(p0, p1, ph[ntl], pl[ntl]);
        splitp(p2, p3, phB[ntl], plB[ntl]);
    }

    // ---- O += P·V (split bf16) over this group's 2 key chunks ----
    const int matk = (lane >> 3) & 1, matn = lane >> 4;
    #pragma unroll
    for (int ckl = 0; ckl < 2; ckl++) {
        const int ck = G * 2 + ckl;
        if (MODE == 1 && ck > wq) continue;
        if (MODE == 2 && ck < wq) continue;
        uint32_t A0 = ph[2*ckl], A1 = phB[2*ckl], A2 = ph[2*ckl+1], A3 = phB[2*ckl+1];
        uint32_t L0 = pl[2*ckl], L1 = plB[2*ckl], L2 = pl[2*ckl+1], L3 = plB[2*ckl+1];
        uint32_t rowoff = (uint32_t)((ck * 16 + matk * 8 + rk) * 128);
        #pragma unroll
        for (int ntd = 0; ntd < 8; ntd += 2) {
            uint32_t base = sb + rowoff + ((uint32_t)((ntd + matn) * 16) ^ xorl);
            uint32_t vh0, vh1, vh2, vh3, vl0, vl1, vl2, vl3;
            ldsm4t(vh0, vh1, vh2, vh3, base + VH);
            ldsm4t(vl0, vl1, vl2, vl3, base + VL);
            mma4(o[ntd],     A0, A1, A2, A3, vh0, vh1);
            mma4(o[ntd + 1], A0, A1, A2, A3, vh2, vh3);
            mma4(o[ntd],     L0, L1, L2, L3, vh0, vh1);
            mma4(o[ntd + 1], L0, L1, L2, L3, vh2, vh3);
            mma4(o[ntd],     A0, A1, A2, A3, vl0, vl1);
            mma4(o[ntd + 1], A0, A1, A2, A3, vl2, vl3);
        }
    }
}

__global__ __launch_bounds__(256, 2) void swa_mma(const float* __restrict__ qkv,
                                                  float* __restrict__ out)
{
    extern __shared__ __align__(1024) char smc[];
    const uint32_t sbu = smem_u32(smc);
    const int tid = threadIdx.x, lane = tid & 31;
    const int wq = (tid >> 5) & 3, G = tid >> 7;      // warp's query quarter, key group
    const int g = lane >> 2, t = lane & 3;
    const int b = blockIdx.y, q0 = blockIdx.x * TQ;
    const float* qkv_b = qkv + (size_t)b * SEQ * 192;

    const int iq0 = q0 + wq * 16 + g, iq1 = iq0 + 8;

    // ---- load Q fragments, scaled, split bf16 hi/lo ----
    const float SCL = 0.125f * 1.44269504088896f;   // 1/sqrt(64) * log2(e)
    uint32_t qh[4][4], ql[4][4];
    {
        const float* qp0 = qkv_b + (size_t)iq0 * 192;
        const float* qp1 = qkv_b + (size_t)iq1 * 192;
        #pragma unroll
        for (int c = 0; c < 4; c++) {
            float2 x0 = *reinterpret_cast<const float2*>(qp0 + c * 16 + 2 * t);
            float2 x1 = *reinterpret_cast<const float2*>(qp1 + c * 16 + 2 * t);
            float2 x2 = *reinterpret_cast<const float2*>(qp0 + c * 16 + 2 * t + 8);
            float2 x3 = *reinterpret_cast<const float2*>(qp1 + c * 16 + 2 * t + 8);
            splitp(x0.x * SCL, x0.y * SCL, qh[c][0], ql[c][0]);
            splitp(x1.x * SCL, x1.y * SCL, qh[c][1], ql[c][1]);
            splitp(x2.x * SCL, x2.y * SCL, qh[c][2], ql[c][2]);
            splitp(x3.x * SCL, x3.y * SCL, qh[c][3], ql[c][3]);
        }
    }

    float o[8][4] = {};
    float l0 = 0.0f, l1 = 0.0f;

    // ---- 3-stage pipelined tile loop; ONE barrier per tile ----
    const int kstart = q0 >= WIN ? q0 - WIN : 0;
    const int n = (q0 - kstart) / 64 + 1;
    const char* gkv = g_kv + ((size_t)(b * (SEQ / 64) + (kstart >> 6))) * BUF;

    prefetch_tile(sbu, gkv, 0, n, tid);
    prefetch_tile(sbu, gkv, 1, n, tid);
    for (int j = 0; j < n; j++) {
        asm volatile("cp.async.wait_group 1;" ::: "memory");   // tile j landed
        __syncthreads();       // data visible to all warps; all finished tile j-1
        prefetch_tile(sbu, gkv, j + 2, n, tid);   // overwrites buffer of j-1: safe
        const int k0 = kstart + 64 * j;
        const uint32_t sb = sbu + (uint32_t)((j % NSTAGE) * BUF);
        const int mode = (q0 >= WIN && j == 0) ? 2 : (k0 == q0 ? 1 : 0);
        if (G == 0) {
            if (mode == 2)      compute_tile<2, 0>(k0, tid, sb, qh, ql, o, l0, l1, iq0, iq1);
            else if (mode == 1) compute_tile<1, 0>(k0, tid, sb, qh, ql, o, l0, l1, iq0, iq1);
            else                compute_tile<0, 0>(k0, tid, sb, qh, ql, o, l0, l1, iq0, iq1);
        } else {
            if (mode == 2)      compute_tile<2, 1>(k0, tid, sb, qh, ql, o, l0, l1, iq0, iq1);
            else if (mode == 1) compute_tile<1, 1>(k0, tid, sb, qh, ql, o, l0, l1, iq0, iq1);
            else                compute_tile<0, 1>(k0, tid, sb, qh, ql, o, l0, l1, iq0, iq1);
        }
    }

    // ---- reduce l across the 4 lanes sharing a row ----
    l0 += __shfl_xor_sync(0xffffffffu, l0, 1);
    l0 += __shfl_xor_sync(0xffffffffu, l0, 2);
    l1 += __shfl_xor_sync(0xffffffffu, l1, 1);
    l1 += __shfl_xor_sync(0xffffffffu, l1, 2);

    // ---- intra-CTA merge of the two key groups via smem ----
    __syncthreads();           // all warps done reading tile buffers (overlap w/ merge scratch)
    float* ms = reinterpret_cast<float*>(smc);          // 64 rows x SMROW floats
    float* lb = ms + 64 * SMROW;                        // 64 floats
    if (G == 1) {
        float* base = ms + (wq * 16) * SMROW;
        #pragma unroll
        for (int nt = 0; nt < 8; nt++) {
            *reinterpret_cast<float2*>(base + g * SMROW + nt * 8 + 2 * t) =
                make_float2(o[nt][0], o[nt][1]);
            *reinterpret_cast<float2*>(base + (g + 8) * SMROW + nt * 8 + 2 * t) =
                make_float2(o[nt][2], o[nt][3]);
        }
        if (t == 0) { lb[wq * 16 + g] = l0; lb[wq * 16 + g + 8] = l1; }
    }
    __syncthreads();
    if (G == 0) {
        const float* base = ms + (wq * 16) * SMROW;
        float rl0 = 1.0f / (l0 + lb[wq * 16 + g]);
        float rl1 = 1.0f / (l1 + lb[wq * 16 + g + 8]);
        float* o0 = out + (size_t)(b * SEQ + iq0) * 64 + 2 * t;
        float* o1 = out + (size_t)(b * SEQ + iq1) * 64 + 2 * t;
        #pragma unroll
        for (int nt = 0; nt < 8; nt++) {
            float2 a = *reinterpret_cast<const float2*>(base + g * SMROW + nt * 8 + 2 * t);
            float2 c = *reinterpret_cast<const float2*>(base + (g + 8) * SMROW + nt * 8 + 2 * t);
            *reinterpret_cast<float2*>(o0 + nt * 8) =
                make_float2((o[nt][0] + a.x) * rl0, (o[nt][1] + a.y) * rl0);
            *reinterpret_cast<float2*>(o1 + nt * 8) =
                make_float2((o[nt][2] + c.x) * rl1, (o[nt][3] + c.y) * rl1);
        }
    }
}

extern "C" void kernel_launch(void* const* d_in, const int* in_sizes, int n_in,
                              void* d_out, int out_size)
{
    const float* qkv = (const float*)d_in[0];
    float* out = (float*)d_out;
    int B = in_sizes[0] / (SEQ * 192);
    static bool configured = false;
    if (!configured) {
        cudaFuncSetAttribute(swa_mma, cudaFuncAttributeMaxDynamicSharedMemorySize, SMEM_TOTAL);
        configured = true;
    }
    dim3 cgrid(SEQ / 64, B);
    conv_kernel<<<cgrid, 256>>>(qkv);
    dim3 grid(SEQ / TQ, B);
    swa_mma<<<grid, 256, SMEM_TOTAL>>>(qkv, out);
}

// round 13
// speedup vs baseline: 1.1317x; 1.1317x over previous
#include <cuda_runtime.h>
#include <cuda_bf16.h>
#include <cstdint>
#include <cstring>

#define SEQ 4096
#define TQ  64
#define WIN 256
#define NB  4

// per-stage smem offsets (bf16 tiles, swizzled images)
#define KH 0
#define KL 8192
#define VH 16384
#define VL 24576
#define BUF 32768
#define NSTAGE 3
#define SMEM_TOTAL (NSTAGE * BUF)

// precomputed bf16 hi/lo K/V tiles, stored as exact swizzled smem images
__device__ char g_kv[(size_t)NB * (SEQ / 64) * BUF];

__device__ __forceinline__ uint32_t smem_u32(const void* p) {
    uint32_t a;
    asm("{ .reg .u64 t; cvta.to.shared.u64 t, %1; cvt.u32.u64 %0, t; }" : "=r"(a) : "l"(p));
    return a;
}
__device__ __forceinline__ float ex2(float x) {
    float r; asm("ex2.approx.ftz.f32 %0, %1;" : "=f"(r) : "f"(x)); return r;
}
__device__ __forceinline__ void ldsm4(uint32_t& r0, uint32_t& r1, uint32_t& r2, uint32_t& r3, uint32_t a) {
    asm volatile("ldmatrix.sync.aligned.m8n8.x4.shared.b16 {%0,%1,%2,%3}, [%4];"
                 : "=r"(r0), "=r"(r1), "=r"(r2), "=r"(r3) : "r"(a));
}
__device__ __forceinline__ void ldsm4t(uint32_t& r0, uint32_t& r1, uint32_t& r2, uint32_t& r3, uint32_t a) {
    asm volatile("ldmatrix.sync.aligned.m8n8.x4.trans.shared.b16 {%0,%1,%2,%3}, [%4];"
                 : "=r"(r0), "=r"(r1), "=r"(r2), "=r"(r3) : "r"(a));
}
__device__ __forceinline__ void mma4(float (&d)[4], uint32_t a0, uint32_t a1, uint32_t a2, uint32_t a3,
                                     uint32_t b0, uint32_t b1) {
    asm volatile("mma.sync.aligned.m16n8k16.row.col.f32.bf16.bf16.f32 "
                 "{%0,%1,%2,%3}, {%4,%5,%6,%7}, {%8,%9}, {%0,%1,%2,%3};"
                 : "+f"(d[0]), "+f"(d[1]), "+f"(d[2]), "+f"(d[3])
                 : "r"(a0), "r"(a1), "r"(a2), "r"(a3), "r"(b0), "r"(b1));
}
__device__ __forceinline__ uint32_t packbf(float x, float y) {
    __nv_bfloat162 v = __floats2bfloat162_rn(x, y);
    uint32_t u; memcpy(&u, &v, 4); return u;
}
__device__ __forceinline__ void splitp(float x, float y, uint32_t& h, uint32_t& l) {
    __nv_bfloat16 hx = __float2bfloat16(x), hy = __float2bfloat16(y);
    h = ((uint32_t)__bfloat16_as_ushort(hy) << 16) | __bfloat16_as_ushort(hx);
    l = packbf(x - __bfloat162float(hx), y - __bfloat162float(hy));
}

// ---- precompute: fp32 K/V -> bf16 hi/lo swizzled tile images (coalesced) ----
__global__ __launch_bounds__(256) void conv_kernel(const float* __restrict__ qkv)
{
    const int ti = blockIdx.x, b = blockIdx.y, tid = threadIdx.x;
    char* tb = g_kv + ((size_t)(b * (SEQ / 64) + ti)) * BUF;
    const float* qb = qkv + ((size_t)b * SEQ + ti * 64) * 192;
    #pragma unroll
    for (int i = 0; i < 8; i++) {
        int L = tid + i * 256;                 // linear float4 index, 0..2047
        int col4 = L & 15;                     // 16 float4 per row-half
        int row  = (L >> 4) & 63;
        int isV  = L >> 10;
        float4 f = *reinterpret_cast<const float4*>(
            qb + (size_t)row * 192 + 64 + isV * 64 + col4 * 4);
        uint32_t h0, l0, h1, l1;
        splitp(f.x, f.y, h0, l0);
        splitp(f.z, f.w, h1, l1);
        uint32_t off = (uint32_t)(row * 128 + col4 * 8);
        uint32_t sw  = off ^ (((uint32_t)(row & 7)) << 4);
        char* base = tb + (isV ? VH : KH);
        *reinterpret_cast<uint2*>(base + sw)        = make_uint2(h0, h1);
        *reinterpret_cast<uint2*>(base + 8192 + sw) = make_uint2(l0, l1);
    }
}

// async copy of one precomputed 32KB tile image into an smem stage (128 thr).
// ALWAYS commits a group (possibly empty) so wait_group counting stays aligned.
__device__ __forceinline__ void prefetch_tile(uint32_t sbu, const char* gkv,
                                              int j, int n, int tid) {
    if (j < n) {
        uint32_t dst = sbu + (uint32_t)((j % NSTAGE) * BUF);
        const char* src = gkv + (size_t)j * BUF;
        #pragma unroll
        for (int c = 0; c < 16; c++) {
            uint32_t off = (uint32_t)(tid * 16 + c * 2048);
            asm volatile("cp.async.cg.shared.global [%0], [%1], 16;"
                         :: "r"(dst + off), "l"(src + off));
        }
    }
    asm volatile("cp.async.commit_group;" ::: "memory");
}

// MODE: 0 unmasked, 1 diagonal (valid j<=iq), 2 lowest (valid j>=iq-WIN)
template<int MODE>
__device__ __forceinline__ void compute_tile(int k0, int tid, uint32_t sb,
                                             const uint32_t (&qh)[4][4], const uint32_t (&ql)[4][4],
                                             float (&o)[8][4], float& l0acc, float& l1acc,
                                             int iq0, int iq1)
{
    const int lane = tid & 31, w = tid >> 5;
    const int t = lane & 3;
    const int rk = lane & 7;
    const uint32_t xorl = rk << 4;
    const uint32_t m16  = (lane >> 3) * 16;

    // ---- S = Q·K^T (split bf16: Qh*Kh + Ql*Kh + Qh*Kl) ----
    float s[8][4] = {};
    #pragma unroll
    for (int c = 0; c < 4; c += 2) {
        #pragma unroll
        for (int nt = 0; nt < 8; nt++) {
            if (MODE == 1 && nt >= 2 * w + 2) continue;
            if (MODE == 2 && nt < 2 * w) continue;
            uint32_t base = sb + (uint32_t)(nt * 1024 + rk * 128) + ((uint32_t)(c * 32 + m16) ^ xorl);
            uint32_t kh0, kh1, kh2, kh3, kl0, kl1, kl2, kl3;
            ldsm4(kh0, kh1, kh2, kh3, base + KH);
            ldsm4(kl0, kl1, kl2, kl3, base + KL);
            mma4(s[nt], qh[c][0], qh[c][1], qh[c][2], qh[c][3], kh0, kh1);
            mma4(s[nt], qh[c+1][0], qh[c+1][1], qh[c+1][2], qh[c+1][3], kh2, kh3);
            mma4(s[nt], ql[c][0], ql[c][1], ql[c][2], ql[c][3], kh0, kh1);
            mma4(s[nt], ql[c+1][0], ql[c+1][1], ql[c+1][2], ql[c+1][3], kh2, kh3);
            mma4(s[nt], qh[c][0], qh[c][1], qh[c][2], qh[c][3], kl0, kl1);
            mma4(s[nt], qh[c+1][0], qh[c+1][1], qh[c+1][2], qh[c+1][3], kl2, kl3);
        }
    }

    // ---- softmax (static max): p = valid ? 2^s : 0; split to bf16 hi/lo ----
    uint32_t ph[8], phB[8], pl[8], plB[8];
    #pragma unroll
    for (int nt = 0; nt < 8; nt++) {
        int j0 = k0 + nt * 8 + 2 * t, j1 = j0 + 1;
        bool v00 = true, v01 = true, v10 = true, v11 = true;
        if (MODE == 1) { v00 = j0 <= iq0; v01 = j1 <= iq0; v10 = j0 <= iq1; v11 = j1 <= iq1; }
        if (MODE == 2) { v00 = j0 >= iq0 - WIN; v01 = j1 >= iq0 - WIN;
                         v10 = j0 >= iq1 - WIN; v11 = j1 >= iq1 - WIN; }
        float p0 = v00 ? ex2(s[nt][0]) : 0.0f;
        float p1 = v01 ? ex2(s[nt][1]) : 0.0f;
        float p2 = v10 ? ex2(s[nt][2]) : 0.0f;
        float p3 = v11 ? ex2(s[nt][3]) : 0.0f;
        l0acc += p0 + p1;
        l1acc += p2 + p3;
        splitp(p0, p1, ph[nt], pl[nt]);
        splitp(p2, p3, phB[nt], plB[nt]);
    }

    // ---- O += P·V (split bf16: Ph*Vh + Pl*Vh + Ph*Vl), V via ldmatrix.trans ----
    const int matk = (lane >> 3) & 1, matn = lane >> 4;
    #pragma unroll
    for (int ck = 0; ck < 4; ck++) {
        if (MODE == 1 && ck > w) continue;
        if (MODE == 2 && ck < w) continue;
        uint32_t A0 = ph[2*ck], A1 = phB[2*ck], A2 = ph[2*ck+1], A3 = phB[2*ck+1];
        uint32_t L0 = pl[2*ck], L1 = plB[2*ck], L2 = pl[2*ck+1], L3 = plB[2*ck+1];
        uint32_t rowoff = (uint32_t)((ck * 16 + matk * 8 + rk) * 128);
        #pragma unroll
        for (int ntd = 0; ntd < 8; ntd += 2) {
            uint32_t base = sb + rowoff + ((uint32_t)((ntd + matn) * 16) ^ xorl);
            uint32_t vh0, vh1, vh2, vh3, vl0, vl1, vl2, vl3;
            ldsm4t(vh0, vh1, vh2, vh3, base + VH);
            ldsm4t(vl0, vl1, vl2, vl3, base + VL);
            mma4(o[ntd],     A0, A1, A2, A3, vh0, vh1);
            mma4(o[ntd + 1], A0, A1, A2, A3, vh2, vh3);
            mma4(o[ntd],     L0, L1, L2, L3, vh0, vh1);
            mma4(o[ntd + 1], L0, L1, L2, L3, vh2, vh3);
            mma4(o[ntd],     A0, A1, A2, A3, vl0, vl1);
            mma4(o[ntd + 1], A0, A1, A2, A3, vl2, vl3);
        }
    }
}

__global__ __launch_bounds__(128, 2) void swa_mma(const float* __restrict__ qkv,
                                                  float* __restrict__ out)
{
    extern __shared__ __align__(1024) char smc[];
    const uint32_t sbu = smem_u32(smc);
    const int tid = threadIdx.x, lane = tid & 31, w = tid >> 5;
    const int g = lane >> 2, t = lane & 3;
    const int b = blockIdx.y, q0 = blockIdx.x * TQ;
    const float* qkv_b = qkv + (size_t)b * SEQ * 192;

    const int iq0 = q0 + w * 16 + g, iq1 = iq0 + 8;

    // ---- load Q fragments, scaled, split bf16 hi/lo ----
    const float SCL = 0.125f * 1.44269504088896f;   // 1/sqrt(64) * log2(e)
    uint32_t qh[4][4], ql[4][4];
    {
        const float* qp0 = qkv_b + (size_t)iq0 * 192;
        const float* qp1 = qkv_b + (size_t)iq1 * 192;
        #pragma unroll
        for (int c = 0; c < 4; c++) {
            float2 x0 = *reinterpret_cast<const float2*>(qp0 + c * 16 + 2 * t);
            float2 x1 = *reinterpret_cast<const float2*>(qp1 + c * 16 + 2 * t);
            float2 x2 = *reinterpret_cast<const float2*>(qp0 + c * 16 + 2 * t + 8);
            float2 x3 = *reinterpret_cast<const float2*>(qp1 + c * 16 + 2 * t + 8);
            splitp(x0.x * SCL, x0.y * SCL, qh[c][0], ql[c][0]);
            splitp(x1.x * SCL, x1.y * SCL, qh[c][1], ql[c][1]);
            splitp(x2.x * SCL, x2.y * SCL, qh[c][2], ql[c][2]);
            splitp(x3.x * SCL, x3.y * SCL, qh[c][3], ql[c][3]);
        }
    }

    float o[8][4] = {};
    float l0 = 0.0f, l1 = 0.0f;

    // ---- 3-stage pipelined tile loop; ONE barrier per tile ----
    const int kstart = q0 >= WIN ? q0 - WIN : 0;
    const int n = (q0 - kstart) / 64 + 1;
    const char* gkv = g_kv + ((size_t)(b * (SEQ / 64) + (kstart >> 6))) * BUF;

    prefetch_tile(sbu, gkv, 0, n, tid);
    prefetch_tile(sbu, gkv, 1, n, tid);
    for (int j = 0; j < n; j++) {
        asm volatile("cp.async.wait_group 1;" ::: "memory");   // tile j landed
        __syncthreads();       // data visible; all warps finished tile j-1
        prefetch_tile(sbu, gkv, j + 2, n, tid);   // overwrites buffer of j-1: safe
        const int k0 = kstart + 64 * j;
        const uint32_t sb = sbu + (uint32_t)((j % NSTAGE) * BUF);
        if (q0 >= WIN && j == 0)
            compute_tile<2>(k0, tid, sb, qh, ql, o, l0, l1, iq0, iq1);
        else if (k0 == q0)
            compute_tile<1>(k0, tid, sb, qh, ql, o, l0, l1, iq0, iq1);
        else
            compute_tile<0>(k0, tid, sb, qh, ql, o, l0, l1, iq0, iq1);
    }

    // ---- reduce l across the 4 lanes sharing a row, scale, store ----
    l0 += __shfl_xor_sync(0xffffffffu, l0, 1);
    l0 += __shfl_xor_sync(0xffffffffu, l0, 2);
    l1 += __shfl_xor_sync(0xffffffffu, l1, 1);
    l1 += __shfl_xor_sync(0xffffffffu, l1, 2);
    float rl0 = 1.0f / l0, rl1 = 1.0f / l1;

    float* o0 = out + (size_t)(b * SEQ + iq0) * 64 + 2 * t;
    float* o1 = out + (size_t)(b * SEQ + iq1) * 64 + 2 * t;
    #pragma unroll
    for (int nt = 0; nt < 8; nt++) {
        *reinterpret_cast<float2*>(o0 + nt * 8) = make_float2(o[nt][0] * rl0, o[nt][1] * rl0);
        *reinterpret_cast<float2*>(o1 + nt * 8) = make_float2(o[nt][2] * rl1, o[nt][3] * rl1);
    }
}

extern "C" void kernel_launch(void* const* d_in, const int* in_sizes, int n_in,
                              void* d_out, int out_size)
{
    const float* qkv = (const float*)d_in[0];
    float* out = (float*)d_out;
    int B = in_sizes[0] / (SEQ * 192);
    static bool configured = false;
    if (!configured) {
        cudaFuncSetAttribute(swa_mma, cudaFuncAttributeMaxDynamicSharedMemorySize, SMEM_TOTAL);
        configured = true;
    }
    dim3 cgrid(SEQ / 64, B);
    conv_kernel<<<cgrid, 256>>>(qkv);
    dim3 grid(SEQ / TQ, B);
    swa_mma<<<grid, 128, SMEM_TOTAL>>>(qkv, out);
}

// round 17
// speedup vs baseline: 1.2384x; 1.0943x over previous
#include <cuda_runtime.h>
#include <cuda_fp16.h>
#include <cstdint>
#include <cstring>

#define SEQ 4096
#define TQ  64
#define WIN 256
#define NB  4

// per-stage smem offsets (fp16 tiles, swizzled images)
#define KH 0
#define KL 8192
#define VH 16384
#define VL 24576
#define BUF 32768
#define NSTAGE 3
#define SMEM_TOTAL (NSTAGE * BUF)

// precomputed fp16 hi/lo K/V tiles, stored as exact swizzled smem images
__device__ char g_kv[(size_t)NB * (SEQ / 64) * BUF];

__device__ __forceinline__ uint32_t smem_u32(const void* p) {
    uint32_t a;
    asm("{ .reg .u64 t; cvta.to.shared.u64 t, %1; cvt.u32.u64 %0, t; }" : "=r"(a) : "l"(p));
    return a;
}
__device__ __forceinline__ float ex2(float x) {
    float r; asm("ex2.approx.ftz.f32 %0, %1;" : "=f"(r) : "f"(x)); return r;
}
__device__ __forceinline__ void ldsm4(uint32_t& r0, uint32_t& r1, uint32_t& r2, uint32_t& r3, uint32_t a) {
    asm volatile("ldmatrix.sync.aligned.m8n8.x4.shared.b16 {%0,%1,%2,%3}, [%4];"
                 : "=r"(r0), "=r"(r1), "=r"(r2), "=r"(r3) : "r"(a));
}
__device__ __forceinline__ void ldsm4t(uint32_t& r0, uint32_t& r1, uint32_t& r2, uint32_t& r3, uint32_t a) {
    asm volatile("ldmatrix.sync.aligned.m8n8.x4.trans.shared.b16 {%0,%1,%2,%3}, [%4];"
                 : "=r"(r0), "=r"(r1), "=r"(r2), "=r"(r3) : "r"(a));
}
__device__ __forceinline__ void mma4(float (&d)[4], uint32_t a0, uint32_t a1, uint32_t a2, uint32_t a3,
                                     uint32_t b0, uint32_t b1) {
    asm volatile("mma.sync.aligned.m16n8k16.row.col.f32.f16.f16.f32 "
                 "{%0,%1,%2,%3}, {%4,%5,%6,%7}, {%8,%9}, {%0,%1,%2,%3};"
                 : "+f"(d[0]), "+f"(d[1]), "+f"(d[2]), "+f"(d[3])
                 : "r"(a0), "r"(a1), "r"(a2), "r"(a3), "r"(b0), "r"(b1));
}
__device__ __forceinline__ uint32_t packhf(float x, float y) {
    __half2 v = __floats2half2_rn(x, y);
    uint32_t u; memcpy(&u, &v, 4); return u;
}
__device__ __forceinline__ void splitp(float x, float y, uint32_t& h, uint32_t& l) {
    __half hx = __float2half_rn(x), hy = __float2half_rn(y);
    __half2 hv = __halves2half2(hx, hy);
    memcpy(&h, &hv, 4);
    l = packhf(x - __half2float(hx), y - __half2float(hy));
}

// ---- precompute: fp32 K/V -> fp16 hi/lo swizzled tile images (coalesced) ----
__global__ __launch_bounds__(256) void conv_kernel(const float* __restrict__ qkv)
{
    const int ti = blockIdx.x, b = blockIdx.y, tid = threadIdx.x;
    char* tb = g_kv + ((size_t)(b * (SEQ / 64) + ti)) * BUF;
    const float* qb = qkv + ((size_t)b * SEQ + ti * 64) * 192;
    #pragma unroll
    for (int i = 0; i < 8; i++) {
        int L = tid + i * 256;                 // linear float4 index, 0..2047
        int col4 = L & 15;                     // 16 float4 per row-half
        int row  = (L >> 4) & 63;
        int isV  = L >> 10;
        float4 f = *reinterpret_cast<const float4*>(
            qb + (size_t)row * 192 + 64 + isV * 64 + col4 * 4);
        uint32_t h0, l0, h1, l1;
        splitp(f.x, f.y, h0, l0);
        splitp(f.z, f.w, h1, l1);
        uint32_t off = (uint32_t)(row * 128 + col4 * 8);
        uint32_t sw  = off ^ (((uint32_t)(row & 7)) << 4);
        char* base = tb + (isV ? VH : KH);
        *reinterpret_cast<uint2*>(base + sw)        = make_uint2(h0, h1);
        *reinterpret_cast<uint2*>(base + 8192 + sw) = make_uint2(l0, l1);
    }
}

// async copy of one precomputed 32KB tile image into an smem stage (128 thr).
// ALWAYS commits a group (possibly empty) so wait_group counting stays aligned.
__device__ __forceinline__ void prefetch_tile(uint32_t sbu, const char* gkv,
                                              int j, int n, int tid) {
    if (j < n) {
        uint32_t dst = sbu + (uint32_t)((j % NSTAGE) * BUF);
        const char* src = gkv + (size_t)j * BUF;
        #pragma unroll
        for (int c = 0; c < 16; c++) {
            uint32_t off = (uint32_t)(tid * 16 + c * 2048);
            asm volatile("cp.async.cg.shared.global [%0], [%1], 16;"
                         :: "r"(dst + off), "l"(src + off));
        }
    }
    asm volatile("cp.async.commit_group;" ::: "memory");
}

// MODE: 0 unmasked, 1 diagonal (valid j<=iq), 2 lowest (valid j>=iq-WIN)
// fp16 asymmetric split: S = Qh*Kh + Ql*Kh + Qh*Kl (full correction, residual ~2^-22);
//                        O += Ph*(Vh+Vl) with P at single fp16 (measured-scaled ~4e-4).
template<int MODE>
__device__ __forceinline__ void compute_tile(int k0, int tid, uint32_t sb,
                                             const uint32_t (&qh)[4][4], const uint32_t (&ql)[4][4],
                                             float (&o)[8][4], float& l0acc, float& l1acc,
                                             int iq0, int iq1)
{
    const int lane = tid & 31, w = tid >> 5;
    const int t = lane & 3;
    const int rk = lane & 7;
    const uint32_t xorl = rk << 4;
    const uint32_t m16  = (lane >> 3) * 16;

    // ---- S = Qh·Kh + Ql·Kh + Qh·Kl ----
    float s[8][4] = {};
    #pragma unroll
    for (int c = 0; c < 4; c += 2) {
        #pragma unroll
        for (int nt = 0; nt < 8; nt++) {
            if (MODE == 1 && nt >= 2 * w + 2) continue;
            if (MODE == 2 && nt < 2 * w) continue;
            uint32_t base = sb + (uint32_t)(nt * 1024 + rk * 128) + ((uint32_t)(c * 32 + m16) ^ xorl);
            uint32_t kh0, kh1, kh2, kh3, kl0, kl1, kl2, kl3;
            ldsm4(kh0, kh1, kh2, kh3, base + KH);
            ldsm4(kl0, kl1, kl2, kl3, base + KL);
            mma4(s[nt], qh[c][0], qh[c][1], qh[c][2], qh[c][3], kh0, kh1);
            mma4(s[nt], qh[c+1][0], qh[c+1][1], qh[c+1][2], qh[c+1][3], kh2, kh3);
            mma4(s[nt], ql[c][0], ql[c][1], ql[c][2], ql[c][3], kh0, kh1);
            mma4(s[nt], ql[c+1][0], ql[c+1][1], ql[c+1][2], ql[c+1][3], kh2, kh3);
            mma4(s[nt], qh[c][0], qh[c][1], qh[c][2], qh[c][3], kl0, kl1);
            mma4(s[nt], qh[c+1][0], qh[c+1][1], qh[c+1][2], qh[c+1][3], kl2, kl3);
        }
    }

    // ---- softmax (static max): p = valid ? 2^s : 0; P at fp16 ----
    uint32_t ph[8], phB[8];
    #pragma unroll
    for (int nt = 0; nt < 8; nt++) {
        int j0 = k0 + nt * 8 + 2 * t, j1 = j0 + 1;
        bool v00 = true, v01 = true, v10 = true, v11 = true;
        if (MODE == 1) { v00 = j0 <= iq0; v01 = j1 <= iq0; v10 = j0 <= iq1; v11 = j1 <= iq1; }
        if (MODE == 2) { v00 = j0 >= iq0 - WIN; v01 = j1 >= iq0 - WIN;
                         v10 = j0 >= iq1 - WIN; v11 = j1 >= iq1 - WIN; }
        float p0 = v00 ? ex2(s[nt][0]) : 0.0f;
        float p1 = v01 ? ex2(s[nt][1]) : 0.0f;
        float p2 = v10 ? ex2(s[nt][2]) : 0.0f;
        float p3 = v11 ? ex2(s[nt][3]) : 0.0f;
        l0acc += p0 + p1;
        l1acc += p2 + p3;
        ph[nt]  = packhf(p0, p1);
        phB[nt] = packhf(p2, p3);
    }

    // ---- O += Ph·Vh + Ph·Vl, V via ldmatrix.trans ----
    const int matk = (lane >> 3) & 1, matn = lane >> 4;
    #pragma unroll
    for (int ck = 0; ck < 4; ck++) {
        if (MODE == 1 && ck > w) continue;
        if (MODE == 2 && ck < w) continue;
        uint32_t A0 = ph[2*ck], A1 = phB[2*ck], A2 = ph[2*ck+1], A3 = phB[2*ck+1];
        uint32_t rowoff = (uint32_t)((ck * 16 + matk * 8 + rk) * 128);
        #pragma unroll
        for (int ntd = 0; ntd < 8; ntd += 2) {
            uint32_t base = sb + rowoff + ((uint32_t)((ntd + matn) * 16) ^ xorl);
            uint32_t vh0, vh1, vh2, vh3, vl0, vl1, vl2, vl3;
            ldsm4t(vh0, vh1, vh2, vh3, base + VH);
            ldsm4t(vl0, vl1, vl2, vl3, base + VL);
            mma4(o[ntd],     A0, A1, A2, A3, vh0, vh1);
            mma4(o[ntd + 1], A0, A1, A2, A3, vh2, vh3);
            mma4(o[ntd],     A0, A1, A2, A3, vl0, vl1);
            mma4(o[ntd + 1], A0, A1, A2, A3, vl2, vl3);
        }
    }
}

__global__ __launch_bounds__(128, 2) void swa_mma(const float* __restrict__ qkv,
                                                  float* __restrict__ out)
{
    extern __shared__ __align__(1024) char smc[];
    const uint32_t sbu = smem_u32(smc);
    const int tid = threadIdx.x, lane = tid & 31, w = tid >> 5;
    const int g = lane >> 2, t = lane & 3;
    const int b = blockIdx.y, q0 = blockIdx.x * TQ;
    const float* qkv_b = qkv + (size_t)b * SEQ * 192;

    const int iq0 = q0 + w * 16 + g, iq1 = iq0 + 8;

    // ---- load Q fragments, scaled, split fp16 hi/lo ----
    const float SCL = 0.125f * 1.44269504088896f;   // 1/sqrt(64) * log2(e)
    uint32_t qh[4][4], ql[4][4];
    {
        const float* qp0 = qkv_b + (size_t)iq0 * 192;
        const float* qp1 = qkv_b + (size_t)iq1 * 192;
        #pragma unroll
        for (int c = 0; c < 4; c++) {
            float2 x0 = *reinterpret_cast<const float2*>(qp0 + c * 16 + 2 * t);
            float2 x1 = *reinterpret_cast<const float2*>(qp1 + c * 16 + 2 * t);
            float2 x2 = *reinterpret_cast<const float2*>(qp0 + c * 16 + 2 * t + 8);
            float2 x3 = *reinterpret_cast<const float2*>(qp1 + c * 16 + 2 * t + 8);
            splitp(x0.x * SCL, x0.y * SCL, qh[c][0], ql[c][0]);
            splitp(x1.x * SCL, x1.y * SCL, qh[c][1], ql[c][1]);
            splitp(x2.x * SCL, x2.y * SCL, qh[c][2], ql[c][2]);
            splitp(x3.x * SCL, x3.y * SCL, qh[c][3], ql[c][3]);
        }
    }

    float o[8][4] = {};
    float l0 = 0.0f, l1 = 0.0f;

    // ---- 3-stage pipelined tile loop; ONE barrier per tile ----
    const int kstart = q0 >= WIN ? q0 - WIN : 0;
    const int n = (q0 - kstart) / 64 + 1;
    const char* gkv = g_kv + ((size_t)(b * (SEQ / 64) + (kstart >> 6))) * BUF;

    prefetch_tile(sbu, gkv, 0, n, tid);
    prefetch_tile(sbu, gkv, 1, n, tid);
    for (int j = 0; j < n; j++) {
        asm volatile("cp.async.wait_group 1;" ::: "memory");   // tile j landed
        __syncthreads();       // data visible; all warps finished tile j-1
        prefetch_tile(sbu, gkv, j + 2, n, tid);   // overwrites buffer of j-1: safe
        const int k0 = kstart + 64 * j;
        const uint32_t sb = sbu + (uint32_t)((j % NSTAGE) * BUF);
        if (q0 >= WIN && j == 0)
            compute_tile<2>(k0, tid, sb, qh, ql, o, l0, l1, iq0, iq1);
        else if (k0 == q0)
            compute_tile<1>(k0, tid, sb, qh, ql, o, l0, l1, iq0, iq1);
        else
            compute_tile<0>(k0, tid, sb, qh, ql, o, l0, l1, iq0, iq1);
    }

    // ---- reduce l across the 4 lanes sharing a row, scale, store ----
    l0 += __shfl_xor_sync(0xffffffffu, l0, 1);
    l0 += __shfl_xor_sync(0xffffffffu, l0, 2);
    l1 += __shfl_xor_sync(0xffffffffu, l1, 1);
    l1 += __shfl_xor_sync(0xffffffffu, l1, 2);
    float rl0 = 1.0f / l0, rl1 = 1.0f / l1;

    float* o0 = out + (size_t)(b * SEQ + iq0) * 64 + 2 * t;
    float* o1 = out + (size_t)(b * SEQ + iq1) * 64 + 2 * t;
    #pragma unroll
    for (int nt = 0; nt < 8; nt++) {
        *reinterpret_cast<float2*>(o0 + nt * 8) = make_float2(o[nt][0] * rl0, o[nt][1] * rl0);
        *reinterpret_cast<float2*>(o1 + nt * 8) = make_float2(o[nt][2] * rl1, o[nt][3] * rl1);
    }
}

extern "C" void kernel_launch(void* const* d_in, const int* in_sizes, int n_in,
                              void* d_out, int out_size)
{
    const float* qkv = (const float*)d_in[0];
    float* out = (float*)d_out;
    int B = in_sizes[0] / (SEQ * 192);
    static bool configured = false;
    if (!configured) {
        cudaFuncSetAttribute(swa_mma, cudaFuncAttributeMaxDynamicSharedMemorySize, SMEM_TOTAL);
        configured = true;
    }
    dim3 cgrid(SEQ / 64, B);
    conv_kernel<<<cgrid, 256>>>(qkv);
    dim3 grid(SEQ / TQ, B);
    swa_mma<<<grid, 128, SMEM_TOTAL>>>(qkv, out);
}